// round 1
// baseline (speedup 1.0000x reference)
#include <cuda_runtime.h>
#include <math_constants.h>

#define H      512
#define NMAX   262144
#define BMAX   4096
#define K1ROWS 8
#define K1GRID (NMAX / K1ROWS)

// ---- scratch (no allocations allowed) ----
__device__ float d_logits[NMAX];
__device__ float d_p[NMAX];
__device__ float d_e[NMAX];
__device__ float d_blockmax[K1GRID];
__device__ int   d_segmax[BMAX];      // float bits, p>0 so int compare is order-preserving
__device__ float d_denom[BMAX];
__device__ int   d_segstart[BMAX + 1];
__device__ float d_gmax;
__device__ float d_Z;
__device__ int   d_is64;

__device__ __forceinline__ int load_batch(const void* bp, int i) {
    if (d_is64) return (int)__ldg(((const long long*)bp) + i);
    return __ldg(((const int*)bp) + i);
}

// batch is sorted 0..B-1 with every id present; last id = B-1 > 0.
// If dtype is int64 (little-endian), int32-view index n-1 (odd, n even) is a
// high word == 0. If int32, it's B-1 != 0.
__global__ void k_detect(const void* batch, int n) {
    d_is64 = (((const int*)batch)[n - 1] == 0) ? 1 : 0;
}

__global__ void k_init(int n, int B) {
    int i = blockIdx.x * blockDim.x + threadIdx.x;
    if (i < B) { d_segmax[i] = 0; d_denom[i] = 0.0f; }
    if (i == 0) { d_Z = 0.0f; d_segstart[B] = n; }
}

__global__ void k_seg(const void* batch, int n) {
    int i = blockIdx.x * blockDim.x + threadIdx.x;
    if (i >= n) return;
    int b = load_batch(batch, i);
    int bp = (i == 0) ? -1 : load_batch(batch, i - 1);
    if (b != bp) d_segstart[b] = i;
}

// logits[i] = x[i,:] . W   (bias cancels in the global softmax — skipped)
// one warp per row; 8 rows per 256-thread block; per-block max -> d_blockmax
__global__ void __launch_bounds__(256) k_logits(const float* __restrict__ x,
                                                const float* __restrict__ W, int n) {
    __shared__ float sW[H];
    __shared__ float smax[K1ROWS];
    int tid = threadIdx.x;
    sW[tid]       = W[tid];
    sW[tid + 256] = W[tid + 256];
    __syncthreads();

    int warp = tid >> 5, lane = tid & 31;
    int row  = blockIdx.x * K1ROWS + warp;
    float v = -CUDART_INF_F;
    if (row < n) {
        const float4* xr = (const float4*)(x + (size_t)row * H);
        const float4* w4 = (const float4*)sW;
        float acc = 0.0f;
        #pragma unroll
        for (int k = 0; k < 4; k++) {
            float4 a = xr[lane + 32 * k];
            float4 w = w4[lane + 32 * k];
            acc += a.x * w.x + a.y * w.y + a.z * w.z + a.w * w.w;
        }
        #pragma unroll
        for (int o = 16; o; o >>= 1) acc += __shfl_xor_sync(0xffffffffu, acc, o);
        if (lane == 0) d_logits[row] = acc;
        v = acc;
    }
    if (lane == 0) smax[warp] = v;
    __syncthreads();
    if (tid == 0) {
        float m = smax[0];
        #pragma unroll
        for (int i = 1; i < K1ROWS; i++) m = fmaxf(m, smax[i]);
        d_blockmax[blockIdx.x] = m;
    }
}

__global__ void __launch_bounds__(1024) k_gmax(int nb) {
    __shared__ float sm[1024];
    float m = -CUDART_INF_F;
    for (int i = threadIdx.x; i < nb; i += 1024) m = fmaxf(m, d_blockmax[i]);
    sm[threadIdx.x] = m;
    __syncthreads();
    #pragma unroll
    for (int s = 512; s; s >>= 1) {
        if (threadIdx.x < s) sm[threadIdx.x] = fmaxf(sm[threadIdx.x], sm[threadIdx.x + s]);
        __syncthreads();
    }
    if (threadIdx.x == 0) d_gmax = sm[0];
}

// p = exp(l - gmax); Z = sum p (block partial + atomic); segmax[b] = max p in segment
__global__ void __launch_bounds__(256) k_exp(const void* batch, int n) {
    int i = blockIdx.x * 256 + threadIdx.x;
    float p = 0.0f;
    if (i < n) {
        p = __expf(d_logits[i] - d_gmax);
        d_p[i] = p;
        int b = load_batch(batch, i);
        atomicMax(&d_segmax[b], __float_as_int(p));
    }
    #pragma unroll
    for (int o = 16; o; o >>= 1) p += __shfl_xor_sync(0xffffffffu, p, o);
    __shared__ float ws[8];
    if ((threadIdx.x & 31) == 0) ws[threadIdx.x >> 5] = p;
    __syncthreads();
    if (threadIdx.x < 8) {
        float s = ws[threadIdx.x];
        #pragma unroll
        for (int o = 4; o; o >>= 1) s += __shfl_xor_sync(0x000000ffu, s, o);
        if (threadIdx.x == 0) atomicAdd(&d_Z, s);
    }
}

// s = p/Z ; e = exp(s - max_seg(s)) = exp((p - pmax)/Z) ; denom[b] += e
__global__ void __launch_bounds__(256) k_e(const void* batch, int n) {
    int i = blockIdx.x * 256 + threadIdx.x;
    if (i >= n) return;
    float invZ = 1.0f / d_Z;
    int b = load_batch(batch, i);
    float pmax = __int_as_float(d_segmax[b]);
    float e = __expf((d_p[i] - pmax) * invZ);
    d_e[i] = e;
    atomicAdd(&d_denom[b], e);
}

// out[b,:] = sum_{i in seg b} (e_i/denom_b) * x[i,:]
// one CTA per segment, 128 threads * float4 = 512 cols; 4-row unroll for MLP
__global__ void __launch_bounds__(128) k_out(const float* __restrict__ x,
                                             float* __restrict__ out) {
    int b = blockIdx.x;
    int r   = d_segstart[b];
    int end = d_segstart[b + 1];
    float invd = 1.0f / d_denom[b];
    int t = threadIdx.x;
    const float4* x4 = (const float4*)x;
    float4 acc = make_float4(0.f, 0.f, 0.f, 0.f);
    for (; r + 4 <= end; r += 4) {
        float c0 = d_e[r]     * invd;
        float c1 = d_e[r + 1] * invd;
        float c2 = d_e[r + 2] * invd;
        float c3 = d_e[r + 3] * invd;
        float4 v0 = x4[(size_t)(r)     * 128 + t];
        float4 v1 = x4[(size_t)(r + 1) * 128 + t];
        float4 v2 = x4[(size_t)(r + 2) * 128 + t];
        float4 v3 = x4[(size_t)(r + 3) * 128 + t];
        acc.x += c0 * v0.x + c1 * v1.x + c2 * v2.x + c3 * v3.x;
        acc.y += c0 * v0.y + c1 * v1.y + c2 * v2.y + c3 * v3.y;
        acc.z += c0 * v0.z + c1 * v1.z + c2 * v2.z + c3 * v3.z;
        acc.w += c0 * v0.w + c1 * v1.w + c2 * v2.w + c3 * v3.w;
    }
    for (; r < end; r++) {
        float c = d_e[r] * invd;
        float4 v = x4[(size_t)r * 128 + t];
        acc.x += c * v.x; acc.y += c * v.y; acc.z += c * v.z; acc.w += c * v.w;
    }
    ((float4*)out)[(size_t)b * 128 + t] = acc;
}

extern "C" void kernel_launch(void* const* d_in, const int* in_sizes, int n_in,
                              void* d_out, int out_size) {
    const float* x     = (const float*)d_in[0];
    const void*  batch = d_in[1];
    const float* W     = (const float*)d_in[2];
    float*       out   = (float*)d_out;

    int n = in_sizes[0] / H;      // rows of x (robust vs. batch dtype width)
    int B = out_size   / H;

    k_detect<<<1, 1>>>(batch, n);
    k_init<<<(B + 255) / 256, 256>>>(n, B);
    k_seg<<<(n + 255) / 256, 256>>>(batch, n);

    int g1 = (n + K1ROWS - 1) / K1ROWS;
    k_logits<<<g1, 256>>>(x, W, n);
    k_gmax<<<1, 1024>>>(g1);
    k_exp<<<(n + 255) / 256, 256>>>(batch, n);
    k_e<<<(n + 255) / 256, 256>>>(batch, n);
    k_out<<<B, 128>>>(x, out);
}

// round 2
// speedup vs baseline: 1.0679x; 1.0679x over previous
#include <cuda_runtime.h>
#include <math_constants.h>

#define H      512
#define NMAX   262144
#define BMAX   4096
#define K1ROWS 8
#define K1GRID (NMAX / K1ROWS)

// ---- scratch (no allocations allowed) ----
__device__ float d_logits[NMAX];
__device__ float d_blockmax[K1GRID];
__device__ float d_blocksum[K1GRID];
__device__ int   d_segstart[BMAX + 1];
__device__ float d_gmax;
__device__ float d_invZ;
__device__ int   d_is64;

__device__ __forceinline__ int load_batch(const void* bp, int i) {
    if (d_is64) return (int)__ldg(((const long long*)bp) + i);
    return __ldg(((const int*)bp) + i);
}

// batch is sorted 0..B-1, every id present; last id = B-1 > 0.
// int64 little-endian: int32-view element n*2-1 is a high word == 0.
// int32: element n-1 == B-1 != 0.  (n even, so index n-1 is a high word iff int64.)
__global__ void k_detect(const void* batch, int n, int B) {
    d_is64 = (((const int*)batch)[n - 1] == 0) ? 1 : 0;
    d_segstart[B] = n;
}

// Per row: logit = x[row,:] . W  (bias cancels in the global softmax).
// Per block: blockmax + sum(exp(l - blockmax))  -> log-sum-exp partials.
// Also: segment-start detection for this block's 8 rows (free under DRAM bound).
__global__ void __launch_bounds__(256) k_logits(const float* __restrict__ x,
                                                const float* __restrict__ W,
                                                const void* __restrict__ batch, int n) {
    __shared__ float sW[H];
    __shared__ float smax[K1ROWS];
    int tid = threadIdx.x;
    sW[tid]       = W[tid];
    sW[tid + 256] = W[tid + 256];
    __syncthreads();

    int warp = tid >> 5, lane = tid & 31;
    int row  = blockIdx.x * K1ROWS + warp;
    float v = -CUDART_INF_F;
    if (row < n) {
        const float4* xr = (const float4*)(x + (size_t)row * H);
        const float4* w4 = (const float4*)sW;
        float acc = 0.0f;
        #pragma unroll
        for (int k = 0; k < 4; k++) {
            float4 a = xr[lane + 32 * k];
            float4 w = w4[lane + 32 * k];
            acc += a.x * w.x + a.y * w.y + a.z * w.z + a.w * w.w;
        }
        #pragma unroll
        for (int o = 16; o; o >>= 1) acc += __shfl_xor_sync(0xffffffffu, acc, o);
        if (lane == 0) d_logits[row] = acc;
        v = acc;
    }
    if (lane == 0) smax[warp] = v;

    // segment starts: 8 indices per block
    if (tid < K1ROWS) {
        int i = blockIdx.x * K1ROWS + tid;
        if (i < n) {
            int b  = load_batch(batch, i);
            int bp = (i == 0) ? -1 : load_batch(batch, i - 1);
            if (b != bp) d_segstart[b] = i;
        }
    }
    __syncthreads();
    if (tid == 0) {
        float m = smax[0];
        #pragma unroll
        for (int i = 1; i < K1ROWS; i++) m = fmaxf(m, smax[i]);
        float s = 0.0f;
        if (m > -CUDART_INF_F) {
            #pragma unroll
            for (int i = 0; i < K1ROWS; i++) s += __expf(smax[i] - m);
        }
        d_blockmax[blockIdx.x] = m;
        d_blocksum[blockIdx.x] = s;
    }
}

// gmax = max blockmax;  Z = sum blocksum_j * exp(blockmax_j - gmax)
__global__ void __launch_bounds__(1024) k_reduce(int nb) {
    __shared__ float sm[1024];
    float m = -CUDART_INF_F;
    for (int i = threadIdx.x; i < nb; i += 1024) m = fmaxf(m, d_blockmax[i]);
    sm[threadIdx.x] = m;
    __syncthreads();
    #pragma unroll
    for (int s = 512; s; s >>= 1) {
        if (threadIdx.x < s) sm[threadIdx.x] = fmaxf(sm[threadIdx.x], sm[threadIdx.x + s]);
        __syncthreads();
    }
    float gmax = sm[0];
    __syncthreads();

    float z = 0.0f;
    for (int i = threadIdx.x; i < nb; i += 1024)
        z += d_blocksum[i] * __expf(d_blockmax[i] - gmax);
    sm[threadIdx.x] = z;
    __syncthreads();
    #pragma unroll
    for (int s = 512; s; s >>= 1) {
        if (threadIdx.x < s) sm[threadIdx.x] += sm[threadIdx.x + s];
        __syncthreads();
    }
    if (threadIdx.x == 0) { d_gmax = gmax; d_invZ = 1.0f / sm[0]; }
}

// One CTA per segment.  Everything per-segment is local:
//   pmax = exp(lmax_seg - gmax)            (exp is monotone)
//   c_i  = exp((exp(l_i - gmax) - pmax) * invZ)
//   out  = (sum c_i * x_i) / (sum c_i)
__global__ void __launch_bounds__(128) k_out(const float* __restrict__ x,
                                             float* __restrict__ out) {
    __shared__ float swm[4];
    int b   = blockIdx.x;
    int r0  = d_segstart[b];
    int end = d_segstart[b + 1];
    int t   = threadIdx.x;
    float gmax = d_gmax, invZ = d_invZ;

    // pass 1: segment max logit (cheap: logits stream is 1 MB total)
    float lm = -CUDART_INF_F;
    for (int i = r0 + t; i < end; i += 128) lm = fmaxf(lm, __ldg(&d_logits[i]));
    #pragma unroll
    for (int o = 16; o; o >>= 1) lm = fmaxf(lm, __shfl_xor_sync(0xffffffffu, lm, o));
    if ((t & 31) == 0) swm[t >> 5] = lm;
    __syncthreads();
    float lmax = fmaxf(fmaxf(swm[0], swm[1]), fmaxf(swm[2], swm[3]));
    float pmax = __expf(lmax - gmax);

    // pass 2: weighted sum; coefficients computed redundantly per thread
    // (broadcast logit loads + 2 MUFU/row — noise vs the 512 MB x stream)
    const float4* x4 = (const float4*)x;
    float4 acc = make_float4(0.f, 0.f, 0.f, 0.f);
    float esum = 0.0f;
    int r = r0;
    for (; r + 4 <= end; r += 4) {
        float c0 = __expf((__expf(__ldg(&d_logits[r])     - gmax) - pmax) * invZ);
        float c1 = __expf((__expf(__ldg(&d_logits[r + 1]) - gmax) - pmax) * invZ);
        float c2 = __expf((__expf(__ldg(&d_logits[r + 2]) - gmax) - pmax) * invZ);
        float c3 = __expf((__expf(__ldg(&d_logits[r + 3]) - gmax) - pmax) * invZ);
        esum += c0 + c1 + c2 + c3;
        float4 v0 = x4[(size_t)(r)     * 128 + t];
        float4 v1 = x4[(size_t)(r + 1) * 128 + t];
        float4 v2 = x4[(size_t)(r + 2) * 128 + t];
        float4 v3 = x4[(size_t)(r + 3) * 128 + t];
        acc.x += c0 * v0.x + c1 * v1.x + c2 * v2.x + c3 * v3.x;
        acc.y += c0 * v0.y + c1 * v1.y + c2 * v2.y + c3 * v3.y;
        acc.z += c0 * v0.z + c1 * v1.z + c2 * v2.z + c3 * v3.z;
        acc.w += c0 * v0.w + c1 * v1.w + c2 * v2.w + c3 * v3.w;
    }
    for (; r < end; r++) {
        float c = __expf((__expf(__ldg(&d_logits[r]) - gmax) - pmax) * invZ);
        esum += c;
        float4 v = x4[(size_t)r * 128 + t];
        acc.x += c * v.x; acc.y += c * v.y; acc.z += c * v.z; acc.w += c * v.w;
    }
    float invd = 1.0f / esum;
    float4 o4 = make_float4(acc.x * invd, acc.y * invd, acc.z * invd, acc.w * invd);
    ((float4*)out)[(size_t)b * 128 + t] = o4;
}

extern "C" void kernel_launch(void* const* d_in, const int* in_sizes, int n_in,
                              void* d_out, int out_size) {
    const float* x     = (const float*)d_in[0];
    const void*  batch = d_in[1];
    const float* W     = (const float*)d_in[2];
    float*       out   = (float*)d_out;

    int n = in_sizes[0] / H;   // rows of x (robust vs. batch dtype width)
    int B = out_size   / H;

    k_detect<<<1, 1>>>(batch, n, B);
    int g1 = (n + K1ROWS - 1) / K1ROWS;
    k_logits<<<g1, 256>>>(x, W, batch, n);
    k_reduce<<<1, 1024>>>(g1);
    k_out<<<B, 128>>>(x, out);
}

// round 3
// speedup vs baseline: 1.0855x; 1.0165x over previous
#include <cuda_runtime.h>
#include <math_constants.h>

#define H      512
#define NMAX   262144
#define BMAX   4096
#define K1ROWS 8
#define K1GRID (NMAX / K1ROWS)
#define CHUNK  128

// ---- scratch (no allocations allowed) ----
__device__ float d_logits[NMAX];
__device__ float d_blockmax[K1GRID];
__device__ float d_blocksum[K1GRID];
__device__ int   d_segstart[BMAX + 1];
__device__ float d_gmax;
__device__ float d_invZ;

// Per row: logit = x[row,:] . W  (bias cancels in the global softmax).
// Per block: blockmax + sum(exp(l - blockmax))  -> log-sum-exp partials.
// Also: segment-start detection for this block's 8 rows (free under DRAM bound).
// batch dtype sniffed per block: n is even, so int32-view elem n-1 is a high
// word (== 0) iff int64; if int32 it's B-1 != 0.
__global__ void __launch_bounds__(256) k_logits(const float* __restrict__ x,
                                                const float* __restrict__ W,
                                                const void* __restrict__ batch,
                                                int n, int B) {
    __shared__ float sW[H];
    __shared__ float smax[K1ROWS];
    int tid = threadIdx.x;
    sW[tid]       = W[tid];
    sW[tid + 256] = W[tid + 256];
    __syncthreads();

    int warp = tid >> 5, lane = tid & 31;
    int row  = blockIdx.x * K1ROWS + warp;
    float v = -CUDART_INF_F;
    if (row < n) {
        const float4* xr = (const float4*)(x + (size_t)row * H);
        const float4* w4 = (const float4*)sW;
        float acc = 0.0f;
        #pragma unroll
        for (int k = 0; k < 4; k++) {
            float4 a = xr[lane + 32 * k];
            float4 w = w4[lane + 32 * k];
            acc += a.x * w.x + a.y * w.y + a.z * w.z + a.w * w.w;
        }
        #pragma unroll
        for (int o = 16; o; o >>= 1) acc += __shfl_xor_sync(0xffffffffu, acc, o);
        if (lane == 0) d_logits[row] = acc;
        v = acc;
    }
    if (lane == 0) smax[warp] = v;

    // segment starts for this block's rows
    if (tid < K1ROWS) {
        int i = blockIdx.x * K1ROWS + tid;
        if (i < n) {
            int is64 = (((const int*)batch)[n - 1] == 0);
            int bc, bp;
            if (is64) {
                bc = (int)__ldg(((const long long*)batch) + i);
                bp = (i == 0) ? -1 : (int)__ldg(((const long long*)batch) + i - 1);
            } else {
                bc = __ldg(((const int*)batch) + i);
                bp = (i == 0) ? -1 : __ldg(((const int*)batch) + i - 1);
            }
            if (bc != bp) d_segstart[bc] = i;
            if (i == n - 1) d_segstart[B] = n;
        }
    }
    __syncthreads();
    if (tid == 0) {
        float m = smax[0];
        #pragma unroll
        for (int i = 1; i < K1ROWS; i++) m = fmaxf(m, smax[i]);
        float s = 0.0f;
        if (m > -CUDART_INF_F) {
            #pragma unroll
            for (int i = 0; i < K1ROWS; i++) s += __expf(smax[i] - m);
        }
        d_blockmax[blockIdx.x] = m;
        d_blocksum[blockIdx.x] = s;
    }
}

// gmax = max blockmax;  Z = sum blocksum_j * exp(blockmax_j - gmax)
__global__ void __launch_bounds__(1024) k_reduce(int nb) {
    __shared__ float sm[1024];
    float m = -CUDART_INF_F;
    for (int i = threadIdx.x; i < nb; i += 1024) m = fmaxf(m, d_blockmax[i]);
    sm[threadIdx.x] = m;
    __syncthreads();
    #pragma unroll
    for (int s = 512; s; s >>= 1) {
        if (threadIdx.x < s) sm[threadIdx.x] = fmaxf(sm[threadIdx.x], sm[threadIdx.x + s]);
        __syncthreads();
    }
    float gmax = sm[0];
    __syncthreads();

    float z = 0.0f;
    for (int i = threadIdx.x; i < nb; i += 1024)
        z += d_blocksum[i] * __expf(d_blockmax[i] - gmax);
    sm[threadIdx.x] = z;
    __syncthreads();
    #pragma unroll
    for (int s = 512; s; s >>= 1) {
        if (threadIdx.x < s) sm[threadIdx.x] += sm[threadIdx.x + s];
        __syncthreads();
    }
    if (threadIdx.x == 0) { d_gmax = gmax; d_invZ = 1.0f / sm[0]; }
}

// One CTA per segment.
//   pmax = exp(lmax_seg - gmax)                         (exp monotone)
//   c_i  = exp((exp(l_i - gmax) - pmax) * invZ)
//   out  = (sum c_i * x_i) / (sum c_i)
// Coefficients are computed ONCE per row (one thread each) into smem per
// 128-row chunk; the x-streaming loop then only does LDS + LDG + FFMA.
__global__ void __launch_bounds__(128) k_out(const float* __restrict__ x,
                                             float* __restrict__ out) {
    __shared__ float swm[4];
    __shared__ float sc[CHUNK];
    int b   = blockIdx.x;
    int r0  = d_segstart[b];
    int end = d_segstart[b + 1];
    int t   = threadIdx.x;
    float gmax = d_gmax, invZ = d_invZ;

    // pass 1: segment max logit
    float lm = -CUDART_INF_F;
    for (int i = r0 + t; i < end; i += 128) lm = fmaxf(lm, __ldg(&d_logits[i]));
    #pragma unroll
    for (int o = 16; o; o >>= 1) lm = fmaxf(lm, __shfl_xor_sync(0xffffffffu, lm, o));
    if ((t & 31) == 0) swm[t >> 5] = lm;
    __syncthreads();
    float lmax = fmaxf(fmaxf(swm[0], swm[1]), fmaxf(swm[2], swm[3]));
    float pmax = __expf(lmax - gmax);

    const float4* x4 = (const float4*)x;
    float4 acc = make_float4(0.f, 0.f, 0.f, 0.f);
    float esum = 0.0f;

    for (int base = r0; base < end; base += CHUNK) {
        int len = min(CHUNK, end - base);
        __syncthreads();   // protect sc from previous chunk's readers
        if (t < len) {
            float c = __expf((__expf(__ldg(&d_logits[base + t]) - gmax) - pmax) * invZ);
            sc[t] = c;
            esum += c;     // each row's coefficient counted exactly once
        }
        __syncthreads();

        const float4* xb = x4 + (size_t)base * 128 + t;
        int j = 0;
        for (; j + 4 <= len; j += 4) {
            float c0 = sc[j], c1 = sc[j + 1], c2 = sc[j + 2], c3 = sc[j + 3];
            float4 v0 = xb[(size_t)(j)     * 128];
            float4 v1 = xb[(size_t)(j + 1) * 128];
            float4 v2 = xb[(size_t)(j + 2) * 128];
            float4 v3 = xb[(size_t)(j + 3) * 128];
            acc.x += c0 * v0.x + c1 * v1.x + c2 * v2.x + c3 * v3.x;
            acc.y += c0 * v0.y + c1 * v1.y + c2 * v2.y + c3 * v3.y;
            acc.z += c0 * v0.z + c1 * v1.z + c2 * v2.z + c3 * v3.z;
            acc.w += c0 * v0.w + c1 * v1.w + c2 * v2.w + c3 * v3.w;
        }
        for (; j < len; j++) {
            float c = sc[j];
            float4 v = xb[(size_t)j * 128];
            acc.x += c * v.x; acc.y += c * v.y; acc.z += c * v.z; acc.w += c * v.w;
        }
    }

    // block-reduce esum
    #pragma unroll
    for (int o = 16; o; o >>= 1) esum += __shfl_xor_sync(0xffffffffu, esum, o);
    __syncthreads();
    if ((t & 31) == 0) swm[t >> 5] = esum;
    __syncthreads();
    float total = swm[0] + swm[1] + swm[2] + swm[3];
    float invd = 1.0f / total;
    float4 o4 = make_float4(acc.x * invd, acc.y * invd, acc.z * invd, acc.w * invd);
    ((float4*)out)[(size_t)b * 128 + t] = o4;
}

extern "C" void kernel_launch(void* const* d_in, const int* in_sizes, int n_in,
                              void* d_out, int out_size) {
    const float* x     = (const float*)d_in[0];
    const void*  batch = d_in[1];
    const float* W     = (const float*)d_in[2];
    float*       out   = (float*)d_out;

    int n = in_sizes[0] / H;   // rows of x (robust vs. batch dtype width)
    int B = out_size   / H;

    int g1 = (n + K1ROWS - 1) / K1ROWS;
    k_logits<<<g1, 256>>>(x, W, batch, n, B);
    k_reduce<<<1, 1024>>>(g1);
    k_out<<<B, 128>>>(x, out);
}

// round 10
// speedup vs baseline: 1.1274x; 1.0386x over previous
#include <cuda_runtime.h>
#include <math_constants.h>

#define H      512
#define NMAX   262144
#define BMAX   4096
#define K1ROWS 8
#define K1GRID (NMAX / K1ROWS)
#define CHUNK  128

// ---- scratch (no allocations allowed) ----
__device__ float d_logits[NMAX];
__device__ float d_blockmax[K1GRID];
__device__ float d_blocksum[K1GRID];
__device__ int   d_segstart[BMAX + 1];
__device__ float d_gmax;
__device__ float d_invZ;

// Segment starts from sorted batch ids. dtype sniff: n even -> int32-view
// elem n-1 is an int64 high word (==0) iff dtype is int64; else it's B-1 != 0.
__global__ void __launch_bounds__(256) k_seg(const void* __restrict__ batch,
                                             int n, int B) {
    int i = blockIdx.x * 256 + threadIdx.x;
    if (i >= n) return;
    int is64 = (((const int*)batch)[n - 1] == 0);   // broadcast L2 hit
    int bc, bp;
    if (is64) {
        bc = (int)__ldg(((const long long*)batch) + i);
        bp = (i == 0) ? -1 : (int)__ldg(((const long long*)batch) + i - 1);
    } else {
        bc = __ldg(((const int*)batch) + i);
        bp = (i == 0) ? -1 : __ldg(((const int*)batch) + i - 1);
    }
    if (bc != bp) d_segstart[bc] = i;
    if (i == n - 1) d_segstart[B] = n;
}

// Per row: logit = x[row,:] . W  (bias cancels in the global softmax).
// Per block: blockmax + sum(exp(l - blockmax))  (log-sum-exp partials).
// Clean streaming kernel — nothing else rides along.
__global__ void __launch_bounds__(256) k_logits(const float* __restrict__ x,
                                                const float* __restrict__ W, int n) {
    __shared__ float sW[H];
    __shared__ float smax[K1ROWS];
    int tid = threadIdx.x;
    sW[tid]       = W[tid];
    sW[tid + 256] = W[tid + 256];
    __syncthreads();

    int warp = tid >> 5, lane = tid & 31;
    int row  = blockIdx.x * K1ROWS + warp;
    float v = -CUDART_INF_F;
    if (row < n) {
        const float4* xr = (const float4*)(x + (size_t)row * H);
        const float4* w4 = (const float4*)sW;
        float acc = 0.0f;
        #pragma unroll
        for (int k = 0; k < 4; k++) {
            float4 a = __ldcs(&xr[lane + 32 * k]);   // streaming: no L2 reuse possible
            float4 w = w4[lane + 32 * k];
            acc += a.x * w.x + a.y * w.y + a.z * w.z + a.w * w.w;
        }
        #pragma unroll
        for (int o = 16; o; o >>= 1) acc += __shfl_xor_sync(0xffffffffu, acc, o);
        if (lane == 0) d_logits[row] = acc;
        v = acc;
    }
    if (lane == 0) smax[warp] = v;
    __syncthreads();
    if (tid == 0) {
        float m = smax[0];
        #pragma unroll
        for (int i = 1; i < K1ROWS; i++) m = fmaxf(m, smax[i]);
        float s = 0.0f;
        if (m > -CUDART_INF_F) {
            #pragma unroll
            for (int i = 0; i < K1ROWS; i++) s += __expf(smax[i] - m);
        }
        d_blockmax[blockIdx.x] = m;
        d_blocksum[blockIdx.x] = s;
    }
}

// gmax = max blockmax;  Z = sum blocksum_j * exp(blockmax_j - gmax)
__global__ void __launch_bounds__(1024) k_reduce(int nb) {
    __shared__ float sm[1024];
    float m = -CUDART_INF_F;
    for (int i = threadIdx.x; i < nb; i += 1024) m = fmaxf(m, d_blockmax[i]);
    sm[threadIdx.x] = m;
    __syncthreads();
    #pragma unroll
    for (int s = 512; s; s >>= 1) {
        if (threadIdx.x < s) sm[threadIdx.x] = fmaxf(sm[threadIdx.x], sm[threadIdx.x + s]);
        __syncthreads();
    }
    float gmax = sm[0];
    __syncthreads();

    float z = 0.0f;
    for (int i = threadIdx.x; i < nb; i += 1024)
        z += d_blocksum[i] * __expf(d_blockmax[i] - gmax);
    sm[threadIdx.x] = z;
    __syncthreads();
    #pragma unroll
    for (int s = 512; s; s >>= 1) {
        if (threadIdx.x < s) sm[threadIdx.x] += sm[threadIdx.x + s];
        __syncthreads();
    }
    if (threadIdx.x == 0) { d_gmax = gmax; d_invZ = 1.0f / sm[0]; }
}

// One CTA per segment.
//   pmax = exp(lmax_seg - gmax)                     (exp monotone)
//   c_i  = exp((exp(l_i - gmax) - pmax) * invZ)
//   out  = (sum c_i * x_i) / (sum c_i)
// Coefficients computed once per row into smem per 128-row chunk; the x
// streaming loop is LDS + 8 front-batched LDG.128 + FFMA (high MLP).
__global__ void __launch_bounds__(128) k_out(const float* __restrict__ x,
                                             float* __restrict__ out) {
    __shared__ float swm[4];
    __shared__ float sc[CHUNK];
    int b   = blockIdx.x;
    int r0  = d_segstart[b];
    int end = d_segstart[b + 1];
    int t   = threadIdx.x;
    float gmax = d_gmax, invZ = d_invZ;

    // segment max logit
    float lm = -CUDART_INF_F;
    for (int i = r0 + t; i < end; i += 128) lm = fmaxf(lm, __ldg(&d_logits[i]));
    #pragma unroll
    for (int o = 16; o; o >>= 1) lm = fmaxf(lm, __shfl_xor_sync(0xffffffffu, lm, o));
    if ((t & 31) == 0) swm[t >> 5] = lm;
    __syncthreads();
    float lmax = fmaxf(fmaxf(swm[0], swm[1]), fmaxf(swm[2], swm[3]));
    float pmax = __expf(lmax - gmax);

    const float4* x4 = (const float4*)x;
    float4 acc = make_float4(0.f, 0.f, 0.f, 0.f);
    float esum = 0.0f;

    for (int base = r0; base < end; base += CHUNK) {
        int len = min(CHUNK, end - base);
        __syncthreads();
        if (t < len) {
            float c = __expf((__expf(__ldg(&d_logits[base + t]) - gmax) - pmax) * invZ);
            sc[t] = c;
            esum += c;
        }
        __syncthreads();

        const float4* xb = x4 + (size_t)base * 128 + t;
        int j = 0;
        for (; j + 8 <= len; j += 8) {
            float4 v0 = __ldcs(&xb[(size_t)(j)     * 128]);
            float4 v1 = __ldcs(&xb[(size_t)(j + 1) * 128]);
            float4 v2 = __ldcs(&xb[(size_t)(j + 2) * 128]);
            float4 v3 = __ldcs(&xb[(size_t)(j + 3) * 128]);
            float4 v4 = __ldcs(&xb[(size_t)(j + 4) * 128]);
            float4 v5 = __ldcs(&xb[(size_t)(j + 5) * 128]);
            float4 v6 = __ldcs(&xb[(size_t)(j + 6) * 128]);
            float4 v7 = __ldcs(&xb[(size_t)(j + 7) * 128]);
            float c0 = sc[j],     c1 = sc[j + 1], c2 = sc[j + 2], c3 = sc[j + 3];
            float c4 = sc[j + 4], c5 = sc[j + 5], c6 = sc[j + 6], c7 = sc[j + 7];
            acc.x += c0 * v0.x + c1 * v1.x + c2 * v2.x + c3 * v3.x
                   + c4 * v4.x + c5 * v5.x + c6 * v6.x + c7 * v7.x;
            acc.y += c0 * v0.y + c1 * v1.y + c2 * v2.y + c3 * v3.y
                   + c4 * v4.y + c5 * v5.y + c6 * v6.y + c7 * v7.y;
            acc.z += c0 * v0.z + c1 * v1.z + c2 * v2.z + c3 * v3.z
                   + c4 * v4.z + c5 * v5.z + c6 * v6.z + c7 * v7.z;
            acc.w += c0 * v0.w + c1 * v1.w + c2 * v2.w + c3 * v3.w
                   + c4 * v4.w + c5 * v5.w + c6 * v6.w + c7 * v7.w;
        }
        for (; j < len; j++) {
            float c = sc[j];
            float4 v = __ldcs(&xb[(size_t)j * 128]);
            acc.x += c * v.x; acc.y += c * v.y; acc.z += c * v.z; acc.w += c * v.w;
        }
    }

    // block-reduce esum
    #pragma unroll
    for (int o = 16; o; o >>= 1) esum += __shfl_xor_sync(0xffffffffu, esum, o);
    __syncthreads();
    if ((t & 31) == 0) swm[t >> 5] = esum;
    __syncthreads();
    float total = swm[0] + swm[1] + swm[2] + swm[3];
    float invd = 1.0f / total;
    float4 o4 = make_float4(acc.x * invd, acc.y * invd, acc.z * invd, acc.w * invd);
    ((float4*)out)[(size_t)b * 128 + t] = o4;
}

extern "C" void kernel_launch(void* const* d_in, const int* in_sizes, int n_in,
                              void* d_out, int out_size) {
    const float* x     = (const float*)d_in[0];
    const void*  batch = d_in[1];
    const float* W     = (const float*)d_in[2];
    float*       out   = (float*)d_out;

    int n = in_sizes[0] / H;   // rows of x (robust vs. batch dtype width)
    int B = out_size   / H;

    k_seg<<<(n + 255) / 256, 256>>>(batch, n, B);
    int g1 = (n + K1ROWS - 1) / K1ROWS;
    k_logits<<<g1, 256>>>(x, W, n);
    k_reduce<<<1, 1024>>>(g1);
    k_out<<<B, 128>>>(x, out);
}